// round 2
// baseline (speedup 1.0000x reference)
#include <cuda_runtime.h>
#include <math.h>

#define NROI 116
#define NGR  128
#define HID  64
#define EDIM 5
#define INCH 116
#define EMBD 16
#define CIN  (INCH + EMBD)
#define EPG  (NROI * NROI)
#define NNODE (NROI * NGR)
#define RS   68

__device__ float g_hpre[NNODE * HID];
__device__ float g_hA[NNODE * HID];
__device__ float g_hB[NNODE * HID];
__device__ float g_sum[HID];
__device__ float g_sumsq[HID];
__device__ float g_scale[HID];
__device__ float g_shift[HID];
__device__ float g_t[NNODE];
__device__ float g_MS[2];

__device__ __forceinline__ float4 ld4(const float* p) { return *reinterpret_cast<const float4*>(p); }
__device__ __forceinline__ void st4(float* p, float4 v) { *reinterpret_cast<float4*>(p) = v; }
__device__ __forceinline__ float4 fma4(float a, float4 b, float4 c) {
    c.x = fmaf(a, b.x, c.x); c.y = fmaf(a, b.y, c.y);
    c.z = fmaf(a, b.z, c.z); c.w = fmaf(a, b.w, c.w); return c;
}
__device__ __forceinline__ float4 add4(float4 a, float4 b) {
    a.x += b.x; a.y += b.y; a.z += b.z; a.w += b.w; return a;
}
__device__ __forceinline__ float4 relu4(float4 a) {
    a.x = fmaxf(a.x, 0.f); a.y = fmaxf(a.y, 0.f);
    a.z = fmaxf(a.z, 0.f); a.w = fmaxf(a.w, 0.f); return a;
}
__device__ __forceinline__ float4 scale4(float4 a, float f) {
    a.x *= f; a.y *= f; a.z *= f; a.w *= f; return a;
}
__device__ __forceinline__ float4 leaky4(float4 u) {
    float4 r;
    r.x = fmaxf(u.x, 0.f) + 0.2f * fminf(u.x, 0.f);
    r.y = fmaxf(u.y, 0.f) + 0.2f * fminf(u.y, 0.f);
    r.z = fmaxf(u.z, 0.f) + 0.2f * fminf(u.z, 0.f);
    r.w = fmaxf(u.w, 0.f) + 0.2f * fminf(u.w, 0.f);
    return r;
}
__device__ __forceinline__ float4 zero4() { return make_float4(0.f, 0.f, 0.f, 0.f); }

__global__ void k_init() {
    int t = threadIdx.x;
    if (t < HID) { g_sum[t] = 0.f; g_sumsq[t] = 0.f; }
}

__global__ void __launch_bounds__(512) k_encode(
    const float* __restrict__ x, const float* __restrict__ emb,
    const int* __restrict__ gid,
    const float* __restrict__ W, const float* __restrict__ b)
{
    extern __shared__ float sm[];
    float* XC = sm;
    float* WE = XC + NROI * CIN;
    float* HS = WE + CIN * HID;
    float* BS = HS + NROI * RS;
    int g = blockIdx.x, tid = threadIdx.x;

    for (int i = tid; i < CIN * HID; i += 512) WE[i] = W[i];
    if (tid < HID) BS[tid] = b[tid];
    const float* xg = x + (size_t)g * NROI * INCH;
    for (int i = tid; i < NROI * INCH; i += 512) {
        int n = i / INCH, c = i - n * INCH;
        XC[n * CIN + c] = xg[i];
    }
    for (int i = tid; i < NROI * EMBD; i += 512) {
        int n = i / EMBD, k = i - n * EMBD;
        XC[n * CIN + INCH + k] = emb[gid[g * NROI + n] * EMBD + k];
    }
    __syncthreads();

    if (tid < 464) {
        int n = tid >> 2, jg = tid & 3, j0 = jg * 16;
        float4 a[4];
        #pragma unroll
        for (int q = 0; q < 4; q++) a[q] = ld4(BS + j0 + 4 * q);
        const float* xr = XC + n * CIN;
        #pragma unroll 4
        for (int c = 0; c < CIN; c++) {
            float xv = xr[c];
            const float* wr = WE + c * HID + j0;
            a[0] = fma4(xv, ld4(wr), a[0]);
            a[1] = fma4(xv, ld4(wr + 4), a[1]);
            a[2] = fma4(xv, ld4(wr + 8), a[2]);
            a[3] = fma4(xv, ld4(wr + 12), a[3]);
        }
        #pragma unroll
        for (int q = 0; q < 4; q++) a[q] = relu4(a[q]);
        float* hp = g_hpre + ((size_t)g * NROI + n) * HID + j0;
        float* hs = HS + n * RS + j0;
        #pragma unroll
        for (int q = 0; q < 4; q++) { st4(hp + 4 * q, a[q]); st4(hs + 4 * q, a[q]); }
    }
    __syncthreads();

    if (tid < HID) {
        float s1 = 0.f, s2 = 0.f;
        for (int n = 0; n < NROI; n++) {
            float v = HS[n * RS + tid];
            s1 += v; s2 += v * v;
        }
        atomicAdd(&g_sum[tid], s1);
        atomicAdd(&g_sumsq[tid], s2);
    }
}

__global__ void k_bnfin(const float* __restrict__ gg, const float* __restrict__ gb) {
    int j = threadIdx.x;
    if (j < HID) {
        const float invN = 1.0f / (float)NNODE;
        float mu  = g_sum[j] * invN;
        float var = g_sumsq[j] * invN - mu * mu;
        float sc  = gg[j] * rsqrtf(var + 1e-5f);
        g_scale[j] = sc;
        g_shift[j] = gb[j] - mu * sc;
    }
}

__global__ void __launch_bounds__(512) k_gine(
    const float* __restrict__ ea,
    const float* __restrict__ We, const float* __restrict__ be,
    const float* __restrict__ W1, const float* __restrict__ b1,
    const float* __restrict__ W2, const float* __restrict__ b2)
{
    extern __shared__ float sm[];
    float* H   = sm;
    float* AG  = H + NROI * RS;
    float* W1s = AG + NROI * RS;
    float* W2s = W1s + HID * HID;
    float* WEs = W2s + HID * HID;
    float* BEs = WEs + EDIM * HID;
    float* B1s = BEs + HID;
    float* B2s = B1s + HID;
    int g = blockIdx.x, tid = threadIdx.x;

    for (int i = tid; i < HID * HID; i += 512) { W1s[i] = W1[i]; W2s[i] = W2[i]; }
    for (int i = tid; i < EDIM * HID; i += 512) WEs[i] = We[i];
    if (tid < HID) { BEs[tid] = be[tid]; B1s[tid] = b1[tid]; B2s[tid] = b2[tid]; }
    const float* hp = g_hpre + (size_t)g * NROI * HID;
    for (int i = tid; i < NROI * HID; i += 512) {
        int n = i >> 6, j = i & 63;
        H[n * RS + j] = hp[i] * g_scale[j] + g_shift[j];
    }
    __syncthreads();

    int d = tid >> 2, jg = tid & 3, j0 = jg * 16;
    bool valid = (tid < 464);

    if (valid) {
        float4 acc[4], be4[4];
        #pragma unroll
        for (int q = 0; q < 4; q++) { acc[q] = zero4(); be4[q] = ld4(BEs + j0 + 4 * q); }
        const float4* wq = reinterpret_cast<const float4*>(WEs);
        const float* eab = ea + ((size_t)g * EPG + d) * EDIM;
        #pragma unroll 1
        for (int s = 0; s < NROI; s++) {
            const float* ep = eab + s * (NROI * EDIM);
            float e0 = __ldg(ep), e1 = __ldg(ep + 1), e2 = __ldg(ep + 2),
                  e3 = __ldg(ep + 3), e4 = __ldg(ep + 4);
            const float* hr = H + s * RS + j0;
            #pragma unroll
            for (int q = 0; q < 4; q++) {
                float4 p = be4[q];
                p = fma4(e0, wq[0 * 16 + jg * 4 + q], p);
                p = fma4(e1, wq[1 * 16 + jg * 4 + q], p);
                p = fma4(e2, wq[2 * 16 + jg * 4 + q], p);
                p = fma4(e3, wq[3 * 16 + jg * 4 + q], p);
                p = fma4(e4, wq[4 * 16 + jg * 4 + q], p);
                acc[q] = add4(acc[q], relu4(add4(ld4(hr + 4 * q), p)));
            }
        }
        float* agr = AG + d * RS + j0;
        const float* hd = H + d * RS + j0;
        #pragma unroll
        for (int q = 0; q < 4; q++) st4(agr + 4 * q, add4(acc[q], ld4(hd + 4 * q)));
    }
    __syncthreads();

    if (valid) {
        float4 a[4];
        #pragma unroll
        for (int q = 0; q < 4; q++) a[q] = ld4(B1s + j0 + 4 * q);
        const float* inr = AG + d * RS;
        #pragma unroll 4
        for (int c = 0; c < HID; c++) {
            float xv = inr[c];
            const float* wr = W1s + c * HID + j0;
            a[0] = fma4(xv, ld4(wr), a[0]);
            a[1] = fma4(xv, ld4(wr + 4), a[1]);
            a[2] = fma4(xv, ld4(wr + 8), a[2]);
            a[3] = fma4(xv, ld4(wr + 12), a[3]);
        }
        float* hr = H + d * RS + j0;
        #pragma unroll
        for (int q = 0; q < 4; q++) st4(hr + 4 * q, relu4(a[q]));
    }
    __syncthreads();

    if (valid) {
        float4 a[4];
        #pragma unroll
        for (int q = 0; q < 4; q++) a[q] = ld4(B2s + j0 + 4 * q);
        const float* inr = H + d * RS;
        #pragma unroll 4
        for (int c = 0; c < HID; c++) {
            float xv = inr[c];
            const float* wr = W2s + c * HID + j0;
            a[0] = fma4(xv, ld4(wr), a[0]);
            a[1] = fma4(xv, ld4(wr + 4), a[1]);
            a[2] = fma4(xv, ld4(wr + 8), a[2]);
            a[3] = fma4(xv, ld4(wr + 12), a[3]);
        }
        float* og = g_hA + ((size_t)g * NROI + d) * HID + j0;
        #pragma unroll
        for (int q = 0; q < 4; q++) st4(og + 4 * q, relu4(a[q]));
    }
}

__global__ void __launch_bounds__(512) k_gat(
    int layer, const float* __restrict__ ea,
    const float* __restrict__ Wl_all, const float* __restrict__ bl_all,
    const float* __restrict__ Wr_all, const float* __restrict__ br_all,
    const float* __restrict__ att_all, const float* __restrict__ We_all,
    const float* __restrict__ bias_all)
{
    const float* in  = (layer == 0) ? g_hA : g_hB;
    float*       op  = (layer == 0) ? g_hB : g_hA;
    const float* Wl  = Wl_all  + layer * HID * HID;
    const float* bl  = bl_all  + layer * HID;
    const float* Wr  = Wr_all  + layer * HID * HID;
    const float* br  = br_all  + layer * HID;
    const float* att = att_all + layer * HID;
    const float* Wee = We_all  + layer * EDIM * HID;
    const float* bia = bias_all + layer * HID;

    extern __shared__ float sm[];
    float* H   = sm;
    float* XL  = H + NROI * RS;
    float* XR  = XL + NROI * RS;
    float* Ws  = XR + NROI * RS;
    float* WEs = Ws + HID * HID;
    float* ATT = WEs + EDIM * HID;
    float* BV  = ATT + HID;
    float* BI  = BV + HID;
    int g = blockIdx.x, tid = threadIdx.x;

    const float* ing = in + (size_t)g * NROI * HID;
    for (int i = tid; i < NROI * HID; i += 512)
        H[(i >> 6) * RS + (i & 63)] = ing[i];
    for (int i = tid; i < HID * HID; i += 512) Ws[i] = Wl[i];
    for (int i = tid; i < EDIM * HID; i += 512) WEs[i] = Wee[i];
    if (tid < HID) { ATT[tid] = att[tid]; BV[tid] = bl[tid]; BI[tid] = bia[tid]; }
    __syncthreads();

    int nn = tid >> 2, jg = tid & 3, j0 = jg * 16;
    bool valid = (tid < 464);
    int n = valid ? nn : 0;

    if (valid) {
        float4 a[4];
        #pragma unroll
        for (int q = 0; q < 4; q++) a[q] = ld4(BV + j0 + 4 * q);
        const float* hr = H + n * RS;
        #pragma unroll 4
        for (int c = 0; c < HID; c++) {
            float xv = hr[c];
            const float* wr = Ws + c * HID + j0;
            a[0] = fma4(xv, ld4(wr), a[0]);
            a[1] = fma4(xv, ld4(wr + 4), a[1]);
            a[2] = fma4(xv, ld4(wr + 8), a[2]);
            a[3] = fma4(xv, ld4(wr + 12), a[3]);
        }
        float* o = XL + n * RS + j0;
        #pragma unroll
        for (int q = 0; q < 4; q++) st4(o + 4 * q, a[q]);
    }
    __syncthreads();
    for (int i = tid; i < HID * HID; i += 512) Ws[i] = Wr[i];
    if (tid < HID) BV[tid] = br[tid];
    __syncthreads();
    if (valid) {
        float4 a[4];
        #pragma unroll
        for (int q = 0; q < 4; q++) a[q] = ld4(BV + j0 + 4 * q);
        const float* hr = H + n * RS;
        #pragma unroll 4
        for (int c = 0; c < HID; c++) {
            float xv = hr[c];
            const float* wr = Ws + c * HID + j0;
            a[0] = fma4(xv, ld4(wr), a[0]);
            a[1] = fma4(xv, ld4(wr + 4), a[1]);
            a[2] = fma4(xv, ld4(wr + 8), a[2]);
            a[3] = fma4(xv, ld4(wr + 12), a[3]);
        }
        float* o = XR + n * RS + j0;
        #pragma unroll
        for (int q = 0; q < 4; q++) st4(o + 4 * q, a[q]);
    }
    __syncthreads();

    float4 att4[4], xr4[4], acc[4];
    #pragma unroll
    for (int q = 0; q < 4; q++) {
        att4[q] = ld4(ATT + j0 + 4 * q);
        xr4[q]  = ld4(XR + n * RS + j0 + 4 * q);
        acc[q]  = zero4();
    }
    float m = -3.0e38f, sw = 0.f;
    const float4* wq = reinterpret_cast<const float4*>(WEs);
    const float* eab = ea + ((size_t)g * EPG + n) * EDIM;

    #pragma unroll 1
    for (int s = 0; s < NROI; s++) {
        const float* ep = eab + s * (NROI * EDIM);
        float e0 = __ldg(ep), e1 = __ldg(ep + 1), e2 = __ldg(ep + 2),
              e3 = __ldg(ep + 3), e4 = __ldg(ep + 4);
        const float* xlr = XL + s * RS + j0;
        float4 xls[4];
        float part = 0.f;
        #pragma unroll
        for (int q = 0; q < 4; q++) {
            float4 p = zero4();
            p = fma4(e0, wq[0 * 16 + jg * 4 + q], p);
            p = fma4(e1, wq[1 * 16 + jg * 4 + q], p);
            p = fma4(e2, wq[2 * 16 + jg * 4 + q], p);
            p = fma4(e3, wq[3 * 16 + jg * 4 + q], p);
            p = fma4(e4, wq[4 * 16 + jg * 4 + q], p);
            float4 xl = ld4(xlr + 4 * q);
            xls[q] = xl;
            float4 lk = leaky4(add4(add4(xl, xr4[q]), p));
            part = fmaf(att4[q].x, lk.x, part);
            part = fmaf(att4[q].y, lk.y, part);
            part = fmaf(att4[q].z, lk.z, part);
            part = fmaf(att4[q].w, lk.w, part);
        }
        part += __shfl_xor_sync(0xffffffffu, part, 1);
        part += __shfl_xor_sync(0xffffffffu, part, 2);

        float nm = fmaxf(m, part);
        float f  = __expf(m - nm);
        float w  = __expf(part - nm);
        sw = sw * f + w;
        #pragma unroll
        for (int q = 0; q < 4; q++)
            acc[q] = fma4(w, xls[q], scale4(acc[q], f));
        m = nm;
    }

    if (valid) {
        float inv = 1.f / (sw + 1e-16f);
        float* og = op + ((size_t)g * NROI + n) * HID + j0;
        #pragma unroll
        for (int q = 0; q < 4; q++)
            st4(og + 4 * q, relu4(add4(scale4(acc[q], inv), ld4(BI + j0 + 4 * q))));
    }
}

__global__ void __launch_bounds__(512) k_pool1(
    const float* __restrict__ W, const float* __restrict__ b,
    const float* __restrict__ w2)
{
    __shared__ __align__(16) float H[NROI * RS];
    __shared__ __align__(16) float Ws[HID * HID];
    __shared__ __align__(16) float Bs[HID];
    __shared__ __align__(16) float W2s[HID];
    int g = blockIdx.x, tid = threadIdx.x;
    const float* ing = g_hA + (size_t)g * NROI * HID;
    for (int i = tid; i < NROI * HID; i += 512)
        H[(i >> 6) * RS + (i & 63)] = ing[i];
    for (int i = tid; i < HID * HID; i += 512) Ws[i] = W[i];
    if (tid < HID) { Bs[tid] = b[tid]; W2s[tid] = w2[tid]; }
    __syncthreads();

    int nn = tid >> 2, jg = tid & 3, j0 = jg * 16;
    bool valid = (tid < 464);
    int n = valid ? nn : 0;

    float4 a[4];
    #pragma unroll
    for (int q = 0; q < 4; q++) a[q] = ld4(Bs + j0 + 4 * q);
    const float* hr = H + n * RS;
    #pragma unroll 4
    for (int c = 0; c < HID; c++) {
        float xv = hr[c];
        const float* wr = Ws + c * HID + j0;
        a[0] = fma4(xv, ld4(wr), a[0]);
        a[1] = fma4(xv, ld4(wr + 4), a[1]);
        a[2] = fma4(xv, ld4(wr + 8), a[2]);
        a[3] = fma4(xv, ld4(wr + 12), a[3]);
    }
    float part = 0.f;
    #pragma unroll
    for (int q = 0; q < 4; q++) {
        float4 w4 = ld4(W2s + j0 + 4 * q);
        part = fmaf(tanhf(a[q].x), w4.x, part);
        part = fmaf(tanhf(a[q].y), w4.y, part);
        part = fmaf(tanhf(a[q].z), w4.z, part);
        part = fmaf(tanhf(a[q].w), w4.w, part);
    }
    part += __shfl_xor_sync(0xffffffffu, part, 1);
    part += __shfl_xor_sync(0xffffffffu, part, 2);
    if (valid && jg == 0) g_t[g * NROI + nn] = part;
}

__global__ void __launch_bounds__(1024) k_pool2() {
    __shared__ float red[1024];
    int t = threadIdx.x;
    float mx = -3.0e38f;
    for (int i = t; i < NNODE; i += 1024) mx = fmaxf(mx, g_t[i]);
    red[t] = mx;
    __syncthreads();
    for (int o = 512; o > 0; o >>= 1) {
        if (t < o) red[t] = fmaxf(red[t], red[t + o]);
        __syncthreads();
    }
    float M = red[0];
    __syncthreads();
    float s = 0.f;
    for (int i = t; i < NNODE; i += 1024) s += __expf(g_t[i] - M);
    red[t] = s;
    __syncthreads();
    for (int o = 512; o > 0; o >>= 1) {
        if (t < o) red[t] += red[t + o];
        __syncthreads();
    }
    if (t == 0) { g_MS[0] = M; g_MS[1] = red[0]; }
}

__global__ void __launch_bounds__(128) k_pool3(
    const float* __restrict__ l1W, const float* __restrict__ l1b,
    const float* __restrict__ l2W, const float* __restrict__ l2b,
    float* __restrict__ out)
{
    __shared__ float wex[NROI];
    __shared__ float pooled[HID];
    __shared__ float y[NROI];
    int g = blockIdx.x, t = threadIdx.x;
    float M = g_MS[0];
    float invS = 1.f / g_MS[1];
    if (t < NROI) wex[t] = __expf(g_t[g * NROI + t] - M) * invS;
    __syncthreads();
    if (t < HID) {
        float s = 0.f;
        const float* hg = g_hA + (size_t)g * NROI * HID;
        for (int n = 0; n < NROI; n++) s = fmaf(hg[n * HID + t], wex[n], s);
        pooled[t] = s;
    }
    __syncthreads();
    if (t < NROI) {
        float a = l1b[t];
        for (int c = 0; c < HID; c++) a = fmaf(pooled[c], l1W[c * INCH + t], a);
        y[t] = fmaxf(a, 0.f);
    }
    __syncthreads();
    if (t < 2) {
        float o = l2b[t];
        for (int j = 0; j < NROI; j++) o = fmaf(y[j], l2W[j * 2 + t], o);
        out[g * 2 + t] = o;
    }
}

extern "C" void kernel_launch(void* const* d_in, const int* in_sizes, int n_in,
                              void* d_out, int out_size)
{
    const float* x    = (const float*)d_in[0];
    const float* ea   = (const float*)d_in[1];
    const float* emb  = (const float*)d_in[2];
    const float* encW = (const float*)d_in[3];
    const float* encb = (const float*)d_in[4];
    const float* bng  = (const float*)d_in[5];
    const float* bnb  = (const float*)d_in[6];
    const float* gWe  = (const float*)d_in[7];
    const float* gbe  = (const float*)d_in[8];
    const float* gW1  = (const float*)d_in[9];
    const float* gb1  = (const float*)d_in[10];
    const float* gW2  = (const float*)d_in[11];
    const float* gb2  = (const float*)d_in[12];
    const float* aWl  = (const float*)d_in[13];
    const float* abl  = (const float*)d_in[14];
    const float* aWr  = (const float*)d_in[15];
    const float* abr  = (const float*)d_in[16];
    const float* aat  = (const float*)d_in[17];
    const float* aWe  = (const float*)d_in[18];
    const float* abi  = (const float*)d_in[19];
    const float* pW1  = (const float*)d_in[20];
    const float* pb1  = (const float*)d_in[21];
    const float* pw2  = (const float*)d_in[22];
    const float* l1W  = (const float*)d_in[23];
    const float* l1b  = (const float*)d_in[24];
    const float* l2W  = (const float*)d_in[25];
    const float* l2b  = (const float*)d_in[26];
    const int*   gid  = (const int*)d_in[29];
    float* out = (float*)d_out;

    const int smEnc  = (NROI * CIN + CIN * HID + NROI * RS + HID) * 4;
    const int smGine = (2 * NROI * RS + 2 * HID * HID + EDIM * HID + 3 * HID) * 4;
    const int smGat  = (3 * NROI * RS + HID * HID + EDIM * HID + 3 * HID) * 4;
    cudaFuncSetAttribute(k_encode, cudaFuncAttributeMaxDynamicSharedMemorySize, smEnc);
    cudaFuncSetAttribute(k_gine,   cudaFuncAttributeMaxDynamicSharedMemorySize, smGine);
    cudaFuncSetAttribute(k_gat,    cudaFuncAttributeMaxDynamicSharedMemorySize, smGat);

    k_init<<<1, 64>>>();
    k_encode<<<NGR, 512, smEnc>>>(x, emb, gid, encW, encb);
    k_bnfin<<<1, 64>>>(bng, bnb);
    k_gine<<<NGR, 512, smGine>>>(ea, gWe, gbe, gW1, gb1, gW2, gb2);
    k_gat<<<NGR, 512, smGat>>>(0, ea, aWl, abl, aWr, abr, aat, aWe, abi);
    k_gat<<<NGR, 512, smGat>>>(1, ea, aWl, abl, aWr, abr, aat, aWe, abi);
    k_pool1<<<NGR, 512>>>(pW1, pb1, pw2);
    k_pool2<<<1, 1024>>>();
    k_pool3<<<NGR, 128>>>(l1W, l1b, l2W, l2b, out);
}

// round 3
// speedup vs baseline: 1.0256x; 1.0256x over previous
#include <cuda_runtime.h>
#include <math.h>

#define NROI 116
#define NGR  128
#define HID  64
#define EDIM 5
#define INCH 116
#define EMBD 16
#define CIN  (INCH + EMBD)
#define EPG  (NROI * NROI)
#define NNODE (NROI * NGR)
#define RS   68
#define THR  928   // 116 nodes x 8 feature-groups, 29 full warps

__device__ float g_hpre[NNODE * HID];
__device__ float g_hA[NNODE * HID];
__device__ float g_hB[NNODE * HID];
__device__ float g_sum[HID];
__device__ float g_sumsq[HID];
__device__ float g_scale[HID];
__device__ float g_shift[HID];
__device__ float g_t[NNODE];
__device__ float g_MS[2];

__device__ __forceinline__ float4 ld4(const float* p) { return *reinterpret_cast<const float4*>(p); }
__device__ __forceinline__ void st4(float* p, float4 v) { *reinterpret_cast<float4*>(p) = v; }
__device__ __forceinline__ float4 fma4(float a, float4 b, float4 c) {
    c.x = fmaf(a, b.x, c.x); c.y = fmaf(a, b.y, c.y);
    c.z = fmaf(a, b.z, c.z); c.w = fmaf(a, b.w, c.w); return c;
}
__device__ __forceinline__ float4 add4(float4 a, float4 b) {
    a.x += b.x; a.y += b.y; a.z += b.z; a.w += b.w; return a;
}
__device__ __forceinline__ float4 relu4(float4 a) {
    a.x = fmaxf(a.x, 0.f); a.y = fmaxf(a.y, 0.f);
    a.z = fmaxf(a.z, 0.f); a.w = fmaxf(a.w, 0.f); return a;
}
__device__ __forceinline__ float4 scale4(float4 a, float f) {
    a.x *= f; a.y *= f; a.z *= f; a.w *= f; return a;
}
__device__ __forceinline__ float4 leaky4(float4 u) {
    float4 r;
    r.x = fmaxf(u.x, 0.f) + 0.2f * fminf(u.x, 0.f);
    r.y = fmaxf(u.y, 0.f) + 0.2f * fminf(u.y, 0.f);
    r.z = fmaxf(u.z, 0.f) + 0.2f * fminf(u.z, 0.f);
    r.w = fmaxf(u.w, 0.f) + 0.2f * fminf(u.w, 0.f);
    return r;
}
__device__ __forceinline__ float4 zero4() { return make_float4(0.f, 0.f, 0.f, 0.f); }

__global__ void k_init() {
    int t = threadIdx.x;
    if (t < HID) { g_sum[t] = 0.f; g_sumsq[t] = 0.f; }
}

// thread = (node n = tid>>3, feature group jg = tid&7 -> 8 features at j0 = jg*8)
__global__ void __launch_bounds__(THR) k_encode(
    const float* __restrict__ x, const float* __restrict__ emb,
    const int* __restrict__ gid,
    const float* __restrict__ W, const float* __restrict__ b)
{
    extern __shared__ float sm[];
    float* XC = sm;                    // NROI*CIN
    float* WE = XC + NROI * CIN;       // CIN*HID
    float* HS = WE + CIN * HID;        // NROI*RS
    float* BS = HS + NROI * RS;        // HID
    int g = blockIdx.x, tid = threadIdx.x;

    for (int i = tid; i < CIN * HID; i += THR) WE[i] = W[i];
    if (tid < HID) BS[tid] = b[tid];
    const float* xg = x + (size_t)g * NROI * INCH;
    for (int i = tid; i < NROI * INCH; i += THR) {
        int n = i / INCH, c = i - n * INCH;
        XC[n * CIN + c] = xg[i];
    }
    for (int i = tid; i < NROI * EMBD; i += THR) {
        int n = i / EMBD, k = i - n * EMBD;
        XC[n * CIN + INCH + k] = emb[gid[g * NROI + n] * EMBD + k];
    }
    __syncthreads();

    int n = tid >> 3, jg = tid & 7, j0 = jg * 8;
    {
        float4 a0 = ld4(BS + j0), a1 = ld4(BS + j0 + 4);
        const float* xr = XC + n * CIN;
        #pragma unroll 4
        for (int c = 0; c < CIN; c++) {
            float xv = xr[c];
            const float* wr = WE + c * HID + j0;
            a0 = fma4(xv, ld4(wr), a0);
            a1 = fma4(xv, ld4(wr + 4), a1);
        }
        a0 = relu4(a0); a1 = relu4(a1);
        float* hp = g_hpre + ((size_t)g * NROI + n) * HID + j0;
        float* hs = HS + n * RS + j0;
        st4(hp, a0); st4(hp + 4, a1);
        st4(hs, a0); st4(hs + 4, a1);
    }
    __syncthreads();

    if (tid < HID) {
        float s1 = 0.f, s2 = 0.f;
        for (int r = 0; r < NROI; r++) {
            float v = HS[r * RS + tid];
            s1 += v; s2 += v * v;
        }
        atomicAdd(&g_sum[tid], s1);
        atomicAdd(&g_sumsq[tid], s2);
    }
}

__global__ void k_bnfin(const float* __restrict__ gg, const float* __restrict__ gb) {
    int j = threadIdx.x;
    if (j < HID) {
        const float invN = 1.0f / (float)NNODE;
        float mu  = g_sum[j] * invN;
        float var = g_sumsq[j] * invN - mu * mu;
        float sc  = gg[j] * rsqrtf(var + 1e-5f);
        g_scale[j] = sc;
        g_shift[j] = gb[j] - mu * sc;
    }
}

__global__ void __launch_bounds__(THR) k_gine(
    const float* __restrict__ ea,
    const float* __restrict__ We, const float* __restrict__ be,
    const float* __restrict__ W1, const float* __restrict__ b1,
    const float* __restrict__ W2, const float* __restrict__ b2)
{
    extern __shared__ float sm[];
    float* H   = sm;                    // NROI*RS
    float* AG  = H + NROI * RS;         // NROI*RS
    float* W1s = AG + NROI * RS;        // HID*HID
    float* W2s = W1s + HID * HID;       // HID*HID
    float* WEs = W2s + HID * HID;       // EDIM*HID
    float* BEs = WEs + EDIM * HID;      // HID
    float* B1s = BEs + HID;
    float* B2s = B1s + HID;
    int g = blockIdx.x, tid = threadIdx.x;

    for (int i = tid; i < HID * HID; i += THR) { W1s[i] = W1[i]; W2s[i] = W2[i]; }
    if (tid < EDIM * HID) WEs[tid] = We[tid];
    if (tid < HID) { BEs[tid] = be[tid]; B1s[tid] = b1[tid]; B2s[tid] = b2[tid]; }
    const float* hp = g_hpre + (size_t)g * NROI * HID;
    for (int i = tid; i < NROI * HID; i += THR) {
        int n = i >> 6, j = i & 63;
        H[n * RS + j] = hp[i] * g_scale[j] + g_shift[j];
    }
    __syncthreads();

    int d = tid >> 3, jg = tid & 7, j0 = jg * 8;
    const int wi = jg * 2;  // float4 column index within a weight row (16 float4/row)

    // edge aggregation: acc = sum_s relu(H[s] + ea[s,d] @ We + be)
    {
        float4 acc0 = zero4(), acc1 = zero4();
        float4 be0 = ld4(BEs + j0), be1 = ld4(BEs + j0 + 4);
        const float4* wq = reinterpret_cast<const float4*>(WEs);
        const float* eab = ea + ((size_t)g * EPG + d) * EDIM;

        float e0, e1, e2, e3, e4;
        { const float* ep = eab;
          e0 = __ldg(ep); e1 = __ldg(ep + 1); e2 = __ldg(ep + 2);
          e3 = __ldg(ep + 3); e4 = __ldg(ep + 4); }
        #pragma unroll 1
        for (int s = 0; s < NROI; s++) {
            int sn = (s + 1 == NROI) ? 0 : s + 1;
            const float* ep = eab + sn * (NROI * EDIM);
            float f0 = __ldg(ep), f1 = __ldg(ep + 1), f2 = __ldg(ep + 2),
                  f3 = __ldg(ep + 3), f4 = __ldg(ep + 4);
            const float* hr = H + s * RS + j0;
            float4 p0 = be0, p1 = be1;
            p0 = fma4(e0, wq[0 * 16 + wi], p0);  p1 = fma4(e0, wq[0 * 16 + wi + 1], p1);
            p0 = fma4(e1, wq[1 * 16 + wi], p0);  p1 = fma4(e1, wq[1 * 16 + wi + 1], p1);
            p0 = fma4(e2, wq[2 * 16 + wi], p0);  p1 = fma4(e2, wq[2 * 16 + wi + 1], p1);
            p0 = fma4(e3, wq[3 * 16 + wi], p0);  p1 = fma4(e3, wq[3 * 16 + wi + 1], p1);
            p0 = fma4(e4, wq[4 * 16 + wi], p0);  p1 = fma4(e4, wq[4 * 16 + wi + 1], p1);
            acc0 = add4(acc0, relu4(add4(ld4(hr), p0)));
            acc1 = add4(acc1, relu4(add4(ld4(hr + 4), p1)));
            e0 = f0; e1 = f1; e2 = f2; e3 = f3; e4 = f4;
        }
        float* agr = AG + d * RS + j0;
        const float* hd = H + d * RS + j0;
        st4(agr,     add4(acc0, ld4(hd)));
        st4(agr + 4, add4(acc1, ld4(hd + 4)));
    }
    __syncthreads();

    // MLP layer 1
    {
        float4 a0 = ld4(B1s + j0), a1 = ld4(B1s + j0 + 4);
        const float* inr = AG + d * RS;
        #pragma unroll 4
        for (int c = 0; c < HID; c++) {
            float xv = inr[c];
            const float* wr = W1s + c * HID + j0;
            a0 = fma4(xv, ld4(wr), a0);
            a1 = fma4(xv, ld4(wr + 4), a1);
        }
        float* hr = H + d * RS + j0;
        st4(hr, relu4(a0)); st4(hr + 4, relu4(a1));
    }
    __syncthreads();

    // MLP layer 2 -> relu -> g_hA
    {
        float4 a0 = ld4(B2s + j0), a1 = ld4(B2s + j0 + 4);
        const float* inr = H + d * RS;
        #pragma unroll 4
        for (int c = 0; c < HID; c++) {
            float xv = inr[c];
            const float* wr = W2s + c * HID + j0;
            a0 = fma4(xv, ld4(wr), a0);
            a1 = fma4(xv, ld4(wr + 4), a1);
        }
        float* og = g_hA + ((size_t)g * NROI + d) * HID + j0;
        st4(og, relu4(a0)); st4(og + 4, relu4(a1));
    }
}

__global__ void __launch_bounds__(THR) k_gat(
    int layer, const float* __restrict__ ea,
    const float* __restrict__ Wl_all, const float* __restrict__ bl_all,
    const float* __restrict__ Wr_all, const float* __restrict__ br_all,
    const float* __restrict__ att_all, const float* __restrict__ We_all,
    const float* __restrict__ bias_all)
{
    const float* in  = (layer == 0) ? g_hA : g_hB;
    float*       op  = (layer == 0) ? g_hB : g_hA;
    const float* Wl  = Wl_all  + layer * HID * HID;
    const float* bl  = bl_all  + layer * HID;
    const float* Wr  = Wr_all  + layer * HID * HID;
    const float* br  = br_all  + layer * HID;
    const float* att = att_all + layer * HID;
    const float* Wee = We_all  + layer * EDIM * HID;
    const float* bia = bias_all + layer * HID;

    extern __shared__ float sm[];
    float* H   = sm;                    // NROI*RS
    float* XL  = H + NROI * RS;         // NROI*RS
    float* XR  = XL + NROI * RS;        // NROI*RS
    float* Ws  = XR + NROI * RS;        // HID*HID
    float* WEs = Ws + HID * HID;        // EDIM*HID
    float* ATT = WEs + EDIM * HID;      // HID
    float* BV  = ATT + HID;             // HID
    float* BI  = BV + HID;              // HID
    int g = blockIdx.x, tid = threadIdx.x;

    const float* ing = in + (size_t)g * NROI * HID;
    for (int i = tid; i < NROI * HID; i += THR)
        H[(i >> 6) * RS + (i & 63)] = ing[i];
    for (int i = tid; i < HID * HID; i += THR) Ws[i] = Wl[i];
    if (tid < EDIM * HID) WEs[tid] = Wee[tid];
    if (tid < HID) { ATT[tid] = att[tid]; BV[tid] = bl[tid]; BI[tid] = bia[tid]; }
    __syncthreads();

    int n = tid >> 3, jg = tid & 7, j0 = jg * 8;
    const int wi = jg * 2;

    // XL = H @ Wl + bl
    {
        float4 a0 = ld4(BV + j0), a1 = ld4(BV + j0 + 4);
        const float* hr = H + n * RS;
        #pragma unroll 4
        for (int c = 0; c < HID; c++) {
            float xv = hr[c];
            const float* wr = Ws + c * HID + j0;
            a0 = fma4(xv, ld4(wr), a0);
            a1 = fma4(xv, ld4(wr + 4), a1);
        }
        float* o = XL + n * RS + j0;
        st4(o, a0); st4(o + 4, a1);
    }
    __syncthreads();
    for (int i = tid; i < HID * HID; i += THR) Ws[i] = Wr[i];
    if (tid < HID) BV[tid] = br[tid];
    __syncthreads();
    // XR = H @ Wr + br
    {
        float4 a0 = ld4(BV + j0), a1 = ld4(BV + j0 + 4);
        const float* hr = H + n * RS;
        #pragma unroll 4
        for (int c = 0; c < HID; c++) {
            float xv = hr[c];
            const float* wr = Ws + c * HID + j0;
            a0 = fma4(xv, ld4(wr), a0);
            a1 = fma4(xv, ld4(wr + 4), a1);
        }
        float* o = XR + n * RS + j0;
        st4(o, a0); st4(o + 4, a1);
    }
    __syncthreads();

    // edge loop with online softmax (reduce score dot over the 8 lanes of this node)
    float4 att0 = ld4(ATT + j0), att1 = ld4(ATT + j0 + 4);
    float4 xr0  = ld4(XR + n * RS + j0), xr1 = ld4(XR + n * RS + j0 + 4);
    float4 acc0 = zero4(), acc1 = zero4();
    float m = -3.0e38f, sw = 0.f;
    const float4* wq = reinterpret_cast<const float4*>(WEs);
    const float* eab = ea + ((size_t)g * EPG + n) * EDIM;

    float e0, e1, e2, e3, e4;
    { const float* ep = eab;
      e0 = __ldg(ep); e1 = __ldg(ep + 1); e2 = __ldg(ep + 2);
      e3 = __ldg(ep + 3); e4 = __ldg(ep + 4); }
    #pragma unroll 1
    for (int s = 0; s < NROI; s++) {
        int sn = (s + 1 == NROI) ? 0 : s + 1;
        const float* ep = eab + sn * (NROI * EDIM);
        float f0 = __ldg(ep), f1 = __ldg(ep + 1), f2 = __ldg(ep + 2),
              f3 = __ldg(ep + 3), f4 = __ldg(ep + 4);

        float4 p0 = zero4(), p1 = zero4();
        p0 = fma4(e0, wq[0 * 16 + wi], p0);  p1 = fma4(e0, wq[0 * 16 + wi + 1], p1);
        p0 = fma4(e1, wq[1 * 16 + wi], p0);  p1 = fma4(e1, wq[1 * 16 + wi + 1], p1);
        p0 = fma4(e2, wq[2 * 16 + wi], p0);  p1 = fma4(e2, wq[2 * 16 + wi + 1], p1);
        p0 = fma4(e3, wq[3 * 16 + wi], p0);  p1 = fma4(e3, wq[3 * 16 + wi + 1], p1);
        p0 = fma4(e4, wq[4 * 16 + wi], p0);  p1 = fma4(e4, wq[4 * 16 + wi + 1], p1);
        const float* xlr = XL + s * RS + j0;
        float4 xl0 = ld4(xlr), xl1 = ld4(xlr + 4);
        float4 lk0 = leaky4(add4(add4(xl0, xr0), p0));
        float4 lk1 = leaky4(add4(add4(xl1, xr1), p1));
        float part = 0.f;
        part = fmaf(att0.x, lk0.x, part); part = fmaf(att0.y, lk0.y, part);
        part = fmaf(att0.z, lk0.z, part); part = fmaf(att0.w, lk0.w, part);
        part = fmaf(att1.x, lk1.x, part); part = fmaf(att1.y, lk1.y, part);
        part = fmaf(att1.z, lk1.z, part); part = fmaf(att1.w, lk1.w, part);
        part += __shfl_xor_sync(0xffffffffu, part, 1);
        part += __shfl_xor_sync(0xffffffffu, part, 2);
        part += __shfl_xor_sync(0xffffffffu, part, 4);

        float nm = fmaxf(m, part);
        float fac = __expf(m - nm);
        float w   = __expf(part - nm);
        sw = sw * fac + w;
        acc0 = fma4(w, xl0, scale4(acc0, fac));
        acc1 = fma4(w, xl1, scale4(acc1, fac));
        m = nm;
        e0 = f0; e1 = f1; e2 = f2; e3 = f3; e4 = f4;
    }

    {
        float inv = 1.f / (sw + 1e-16f);
        float* og = op + ((size_t)g * NROI + n) * HID + j0;
        st4(og,     relu4(add4(scale4(acc0, inv), ld4(BI + j0))));
        st4(og + 4, relu4(add4(scale4(acc1, inv), ld4(BI + j0 + 4))));
    }
}

__global__ void __launch_bounds__(512) k_pool1(
    const float* __restrict__ W, const float* __restrict__ b,
    const float* __restrict__ w2)
{
    __shared__ __align__(16) float H[NROI * RS];
    __shared__ __align__(16) float Ws[HID * HID];
    __shared__ __align__(16) float Bs[HID];
    __shared__ __align__(16) float W2s[HID];
    int g = blockIdx.x, tid = threadIdx.x;
    const float* ing = g_hA + (size_t)g * NROI * HID;
    for (int i = tid; i < NROI * HID; i += 512)
        H[(i >> 6) * RS + (i & 63)] = ing[i];
    for (int i = tid; i < HID * HID; i += 512) Ws[i] = W[i];
    if (tid < HID) { Bs[tid] = b[tid]; W2s[tid] = w2[tid]; }
    __syncthreads();

    int nn = tid >> 2, jg = tid & 3, j0 = jg * 16;
    bool valid = (tid < 464);
    int n = valid ? nn : 0;

    float4 a[4];
    #pragma unroll
    for (int q = 0; q < 4; q++) a[q] = ld4(Bs + j0 + 4 * q);
    const float* hr = H + n * RS;
    #pragma unroll 4
    for (int c = 0; c < HID; c++) {
        float xv = hr[c];
        const float* wr = Ws + c * HID + j0;
        a[0] = fma4(xv, ld4(wr), a[0]);
        a[1] = fma4(xv, ld4(wr + 4), a[1]);
        a[2] = fma4(xv, ld4(wr + 8), a[2]);
        a[3] = fma4(xv, ld4(wr + 12), a[3]);
    }
    float part = 0.f;
    #pragma unroll
    for (int q = 0; q < 4; q++) {
        float4 w4 = ld4(W2s + j0 + 4 * q);
        part = fmaf(tanhf(a[q].x), w4.x, part);
        part = fmaf(tanhf(a[q].y), w4.y, part);
        part = fmaf(tanhf(a[q].z), w4.z, part);
        part = fmaf(tanhf(a[q].w), w4.w, part);
    }
    part += __shfl_xor_sync(0xffffffffu, part, 1);
    part += __shfl_xor_sync(0xffffffffu, part, 2);
    if (valid && jg == 0) g_t[g * NROI + nn] = part;
}

__global__ void __launch_bounds__(1024) k_pool2() {
    __shared__ float red[1024];
    int t = threadIdx.x;
    float mx = -3.0e38f;
    for (int i = t; i < NNODE; i += 1024) mx = fmaxf(mx, g_t[i]);
    red[t] = mx;
    __syncthreads();
    for (int o = 512; o > 0; o >>= 1) {
        if (t < o) red[t] = fmaxf(red[t], red[t + o]);
        __syncthreads();
    }
    float M = red[0];
    __syncthreads();
    float s = 0.f;
    for (int i = t; i < NNODE; i += 1024) s += __expf(g_t[i] - M);
    red[t] = s;
    __syncthreads();
    for (int o = 512; o > 0; o >>= 1) {
        if (t < o) red[t] += red[t + o];
        __syncthreads();
    }
    if (t == 0) { g_MS[0] = M; g_MS[1] = red[0]; }
}

__global__ void __launch_bounds__(128) k_pool3(
    const float* __restrict__ l1W, const float* __restrict__ l1b,
    const float* __restrict__ l2W, const float* __restrict__ l2b,
    float* __restrict__ out)
{
    __shared__ float wex[NROI];
    __shared__ float pooled[HID];
    __shared__ float y[NROI];
    int g = blockIdx.x, t = threadIdx.x;
    float M = g_MS[0];
    float invS = 1.f / g_MS[1];
    if (t < NROI) wex[t] = __expf(g_t[g * NROI + t] - M) * invS;
    __syncthreads();
    if (t < HID) {
        float s = 0.f;
        const float* hg = g_hA + (size_t)g * NROI * HID;
        for (int n = 0; n < NROI; n++) s = fmaf(hg[n * HID + t], wex[n], s);
        pooled[t] = s;
    }
    __syncthreads();
    if (t < NROI) {
        float a = l1b[t];
        for (int c = 0; c < HID; c++) a = fmaf(pooled[c], l1W[c * INCH + t], a);
        y[t] = fmaxf(a, 0.f);
    }
    __syncthreads();
    if (t < 2) {
        float o = l2b[t];
        for (int j = 0; j < NROI; j++) o = fmaf(y[j], l2W[j * 2 + t], o);
        out[g * 2 + t] = o;
    }
}

extern "C" void kernel_launch(void* const* d_in, const int* in_sizes, int n_in,
                              void* d_out, int out_size)
{
    const float* x    = (const float*)d_in[0];
    const float* ea   = (const float*)d_in[1];
    const float* emb  = (const float*)d_in[2];
    const float* encW = (const float*)d_in[3];
    const float* encb = (const float*)d_in[4];
    const float* bng  = (const float*)d_in[5];
    const float* bnb  = (const float*)d_in[6];
    const float* gWe  = (const float*)d_in[7];
    const float* gbe  = (const float*)d_in[8];
    const float* gW1  = (const float*)d_in[9];
    const float* gb1  = (const float*)d_in[10];
    const float* gW2  = (const float*)d_in[11];
    const float* gb2  = (const float*)d_in[12];
    const float* aWl  = (const float*)d_in[13];
    const float* abl  = (const float*)d_in[14];
    const float* aWr  = (const float*)d_in[15];
    const float* abr  = (const float*)d_in[16];
    const float* aat  = (const float*)d_in[17];
    const float* aWe  = (const float*)d_in[18];
    const float* abi  = (const float*)d_in[19];
    const float* pW1  = (const float*)d_in[20];
    const float* pb1  = (const float*)d_in[21];
    const float* pw2  = (const float*)d_in[22];
    const float* l1W  = (const float*)d_in[23];
    const float* l1b  = (const float*)d_in[24];
    const float* l2W  = (const float*)d_in[25];
    const float* l2b  = (const float*)d_in[26];
    const int*   gid  = (const int*)d_in[29];
    float* out = (float*)d_out;

    const int smEnc  = (NROI * CIN + CIN * HID + NROI * RS + HID) * 4;
    const int smGine = (2 * NROI * RS + 2 * HID * HID + EDIM * HID + 3 * HID) * 4;
    const int smGat  = (3 * NROI * RS + HID * HID + EDIM * HID + 3 * HID) * 4;
    cudaFuncSetAttribute(k_encode, cudaFuncAttributeMaxDynamicSharedMemorySize, smEnc);
    cudaFuncSetAttribute(k_gine,   cudaFuncAttributeMaxDynamicSharedMemorySize, smGine);
    cudaFuncSetAttribute(k_gat,    cudaFuncAttributeMaxDynamicSharedMemorySize, smGat);

    k_init<<<1, 64>>>();
    k_encode<<<NGR, THR, smEnc>>>(x, emb, gid, encW, encb);
    k_bnfin<<<1, 64>>>(bng, bnb);
    k_gine<<<NGR, THR, smGine>>>(ea, gWe, gbe, gW1, gb1, gW2, gb2);
    k_gat<<<NGR, THR, smGat>>>(0, ea, aWl, abl, aWr, abr, aat, aWe, abi);
    k_gat<<<NGR, THR, smGat>>>(1, ea, aWl, abl, aWr, abr, aat, aWe, abi);
    k_pool1<<<NGR, 512>>>(pW1, pb1, pw2);
    k_pool2<<<1, 1024>>>();
    k_pool3<<<NGR, 128>>>(l1W, l1b, l2W, l2b, out);
}